// round 1
// baseline (speedup 1.0000x reference)
#include <cuda_runtime.h>
#include <math.h>

#define A_DIM 20
#define L_DIM 512
#define CH 8
#define B_DIM 1024

// Scratch (allocation-free rule: __device__ globals)
__device__ float g_W[CH * L_DIM];     // composed linear map: out[c] = sum_l W[c*512+l] * h[l]
__device__ float g_V[21 * A_DIM];     // V[i][r], row 20 = zeros (for masked positions)
__device__ float g_vk[3];             // exp(-k^2/(2 std^2)) for k=1,2,3

// ---------------------------------------------------------------------------
// Kernel 0: build V matrix and row kernel values (one tiny block)
// ---------------------------------------------------------------------------
__global__ void prep_kernel(const float* __restrict__ lpm,
                            const float* __restrict__ pm,
                            const float* __restrict__ stdv) {
    int tid = threadIdx.x;
    if (tid < 400) {
        int i = tid / A_DIM, r = tid % A_DIM;
        float v = 0.f;
        if (r > i && r <= A_DIM - 2) {
            float m = fminf(fmaxf(lpm[i * A_DIM + r], 0.001f), 1.0f) * pm[i * A_DIM + r];
            v += m;
        }
        if (r < i) {
            float m = fminf(fmaxf(lpm[r * A_DIM + i], 0.001f), 1.0f) * pm[r * A_DIM + i];
            v += m;
        }
        g_V[tid] = v;
    } else if (tid < 420) {
        g_V[tid] = 0.f;  // row 20: masked positions contribute zero column term
    } else if (tid < 423) {
        int k = tid - 420 + 1;
        float s = stdv[0];
        g_vk[tid - 420] = expf(-(float)(k * k) / (2.f * s * s));
    }
}

// ---------------------------------------------------------------------------
// Kernel 1: compose the conv/pool stack into W (8 x 512).
// Block l0 pushes basis vector e_{l0} through the network.
// ---------------------------------------------------------------------------
__global__ __launch_bounds__(256) void build_w_kernel(const float* __restrict__ w0,
                                                      const float* __restrict__ ws) {
    __shared__ float bufA[CH][L_DIM];
    __shared__ float bufB[CH][L_DIM];
    __shared__ float sws[8 * CH * CH * 3];  // 1536
    __shared__ float sw0[CH * 3];

    int tid = threadIdx.x;
    int l0 = blockIdx.x;

    for (int i = tid; i < 8 * CH * CH * 3; i += 256) sws[i] = ws[i];
    if (tid < CH * 3) sw0[tid] = w0[tid];
    __syncthreads();

    // Layer 0: conv(1->8, k=3, pad 1) applied to e_{l0}: out[c][p] = w0[c][l0-p+1]
    for (int i = tid; i < CH * L_DIM; i += 256) {
        int c = i >> 9, p = i & (L_DIM - 1);
        int t = l0 - p + 1;
        bufA[c][p] = (t >= 0 && t < 3) ? sw0[c * 3 + t] : 0.f;
    }
    __syncthreads();
    // pool 512 -> 256 into bufB
    for (int i = tid; i < CH * 256; i += 256) {
        int c = i >> 8, q = i & 255;
        bufB[c][q] = 0.5f * (bufA[c][2 * q] + bufA[c][2 * q + 1]);
    }
    __syncthreads();

    int Lh = 256;
    // cur = bufB, nxt = bufA, ping-pong: conv cur->nxt, pool nxt->cur
    for (int layer = 0; layer < 8; layer++) {
        const float* w = &sws[layer * CH * CH * 3];
        for (int i = tid; i < CH * Lh; i += 256) {
            int c = i / Lh, p = i % Lh;
            float acc = 0.f;
            #pragma unroll
            for (int ci = 0; ci < CH; ci++) {
                float a0 = (p > 0)      ? bufB[ci][p - 1] : 0.f;
                float a1 =                bufB[ci][p];
                float a2 = (p < Lh - 1) ? bufB[ci][p + 1] : 0.f;
                const float* wc = w + (c * CH + ci) * 3;
                acc += a0 * wc[0] + a1 * wc[1] + a2 * wc[2];
            }
            bufA[c][p] = acc;
        }
        __syncthreads();
        int Lp = Lh >> 1;
        for (int i = tid; i < CH * Lp; i += 256) {
            int c = i / Lp, q = i % Lp;
            bufB[c][q] = 0.5f * (bufA[c][2 * q] + bufA[c][2 * q + 1]);
        }
        __syncthreads();
        Lh = Lp;
    }
    // Lh == 1
    if (tid < CH) g_W[tid * L_DIM + l0] = bufB[tid][0];
}

// ---------------------------------------------------------------------------
// Kernel 2: main. One block per batch element b.
//   decode x -> av[l] (active aa index, or 20 if masked)
//   for each a: build h_a[l] = onehot + V[av,a] + row-stencil, dot with 8 W rows
// ---------------------------------------------------------------------------
__global__ __launch_bounds__(256) void main_kernel(const float* __restrict__ x,
                                                   float* __restrict__ out) {
    __shared__ float Ws[CH][L_DIM];   // 16 KB
    __shared__ float Vs[21 * A_DIM];  // V[i][a]
    __shared__ float hs[L_DIM];
    __shared__ int   av[L_DIM];
    __shared__ float svk[3];

    int tid = threadIdx.x;
    int b = blockIdx.x;

    for (int i = tid; i < CH * L_DIM; i += 256) ((float*)Ws)[i] = g_W[i];
    for (int i = tid; i < 21 * A_DIM; i += 256) Vs[i] = g_V[i];
    if (tid < 3) svk[tid] = g_vk[tid];

    // decode one-hot: av[l] = index of nonzero in x[b,l,:], 20 if none
    const float* xb = x + (size_t)b * (L_DIM * A_DIM);
    for (int l = tid; l < L_DIM; l += 256) {
        const float4* p = (const float4*)(xb + l * A_DIM);  // 80B aligned
        int aa = A_DIM;
        #pragma unroll
        for (int j = 0; j < 5; j++) {
            float4 q = p[j];
            if (q.x != 0.f) aa = 4 * j + 0;
            if (q.y != 0.f) aa = 4 * j + 1;
            if (q.z != 0.f) aa = 4 * j + 2;
            if (q.w != 0.f) aa = 4 * j + 3;
        }
        av[l] = aa;
    }
    __syncthreads();

    float v1 = svk[0], v2 = svk[1], v3 = svk[2];
    int warp = tid >> 5, lane = tid & 31;

    for (int a = 0; a < A_DIM; a++) {
        // build h_a
        for (int l = tid; l < L_DIM; l += 256) {
            int c0 = av[l];
            float h = (c0 == a ? 1.f : 0.f) + Vs[c0 * A_DIM + a];

            bool mk1, mk2, mk3;
            if (l == 0) {
                bool m0 = (av[0] == a), m1 = (av[1] == a), m2 = (av[2] == a), m3 = (av[3] == a);
                mk1 = m0 | m1; mk2 = mk1 | m2; mk3 = mk2 | m3;
            } else if (l == L_DIM - 1) {
                bool m0 = (av[511] == a), m1 = (av[510] == a), m2 = (av[509] == a), m3 = (av[508] == a);
                mk1 = m0 | m1; mk2 = mk1 | m2; mk3 = mk2 | m3;
            } else if (l >= 3 && l <= L_DIM - 4) {
                mk1 = (av[l - 1] == a) | (av[l + 1] == a);
                mk2 = (av[l - 2] == a) | (av[l + 2] == a);
                mk3 = (av[l - 3] == a) | (av[l + 3] == a);
            } else {
                bool p1 = (l >= 1) ? (av[l - 1] == a) : false;
                bool p2 = (l >= 2) ? (av[l - 2] == a) : false;
                bool p3 = (l >= 3) ? (av[l - 3] == a) : false;
                bool n1 = (l <= L_DIM - 2) ? (av[l + 1] == a) : false;
                bool n2 = (l <= L_DIM - 3) ? (av[l + 2] == a) : false;
                bool n3 = (l <= L_DIM - 4) ? (av[l + 3] == a) : false;
                mk1 = p1 | n1; mk2 = p2 | n2; mk3 = p3 | n3;
            }
            h += mk3 ? v3 : (mk2 ? v2 : (mk1 ? v1 : 0.f));
            hs[l] = h;
        }
        __syncthreads();

        // 8 warps: warp c computes out[b,a,c] = W[c,:] . h
        float acc = 0.f;
        #pragma unroll
        for (int i = 0; i < 16; i++) {
            int l = lane + 32 * i;
            acc += Ws[warp][l] * hs[l];
        }
        #pragma unroll
        for (int off = 16; off; off >>= 1) acc += __shfl_xor_sync(0xFFFFFFFFu, acc, off);
        if (lane == 0) out[(size_t)b * (A_DIM * CH) + a * CH + warp] = acc;
        __syncthreads();
    }
}

// ---------------------------------------------------------------------------
// Inputs (metadata order): x, masks(unused), lpm, pm, std, w0, ws
// Output: float32 (B, A, CH) = (1024, 20, 8)
// ---------------------------------------------------------------------------
extern "C" void kernel_launch(void* const* d_in, const int* in_sizes, int n_in,
                              void* d_out, int out_size) {
    const float* x   = (const float*)d_in[0];
    const float* lpm = (const float*)d_in[2];
    const float* pm  = (const float*)d_in[3];
    const float* stdv= (const float*)d_in[4];
    const float* w0  = (const float*)d_in[5];
    const float* ws  = (const float*)d_in[6];
    float* out = (float*)d_out;

    prep_kernel<<<1, 512>>>(lpm, pm, stdv);
    build_w_kernel<<<L_DIM, 256>>>(w0, ws);
    main_kernel<<<B_DIM, 256>>>(x, out);
}

// round 2
// speedup vs baseline: 1.5080x; 1.5080x over previous
#include <cuda_runtime.h>
#include <math.h>

#define A_DIM 20
#define L_DIM 512
#define CH 8
#define B_DIM 1024
#define TPB 160   // 5 warps; warp w owns amino acids 4w..4w+3

__device__ float g_W[CH * L_DIM];   // composed linear map

// ---------------------------------------------------------------------------
// Kernel 1: compose the conv/pool stack into W (8 x 512).
// Block l0 pushes basis vector e_{l0} through the network. (known-good)
// ---------------------------------------------------------------------------
__global__ __launch_bounds__(256) void build_w_kernel(const float* __restrict__ w0,
                                                      const float* __restrict__ ws) {
    __shared__ float bufA[CH][L_DIM];
    __shared__ float bufB[CH][L_DIM];
    __shared__ float sws[8 * CH * CH * 3];
    __shared__ float sw0[CH * 3];

    int tid = threadIdx.x;
    int l0 = blockIdx.x;

    for (int i = tid; i < 8 * CH * CH * 3; i += 256) sws[i] = ws[i];
    if (tid < CH * 3) sw0[tid] = w0[tid];
    __syncthreads();

    for (int i = tid; i < CH * L_DIM; i += 256) {
        int c = i >> 9, p = i & (L_DIM - 1);
        int t = l0 - p + 1;
        bufA[c][p] = (t >= 0 && t < 3) ? sw0[c * 3 + t] : 0.f;
    }
    __syncthreads();
    for (int i = tid; i < CH * 256; i += 256) {
        int c = i >> 8, q = i & 255;
        bufB[c][q] = 0.5f * (bufA[c][2 * q] + bufA[c][2 * q + 1]);
    }
    __syncthreads();

    int Lh = 256;
    for (int layer = 0; layer < 8; layer++) {
        const float* w = &sws[layer * CH * CH * 3];
        for (int i = tid; i < CH * Lh; i += 256) {
            int c = i / Lh, p = i % Lh;
            float acc = 0.f;
            #pragma unroll
            for (int ci = 0; ci < CH; ci++) {
                float a0 = (p > 0)      ? bufB[ci][p - 1] : 0.f;
                float a1 =                bufB[ci][p];
                float a2 = (p < Lh - 1) ? bufB[ci][p + 1] : 0.f;
                const float* wc = w + (c * CH + ci) * 3;
                acc += a0 * wc[0] + a1 * wc[1] + a2 * wc[2];
            }
            bufA[c][p] = acc;
        }
        __syncthreads();
        int Lp = Lh >> 1;
        for (int i = tid; i < CH * Lp; i += 256) {
            int c = i / Lp, q = i % Lp;
            bufB[c][q] = 0.5f * (bufA[c][2 * q] + bufA[c][2 * q + 1]);
        }
        __syncthreads();
        Lh = Lp;
    }
    if (tid < CH) g_W[tid * L_DIM + l0] = bufB[tid][0];
}

// ---------------------------------------------------------------------------
// Kernel 2: main. One block per batch element. Barrier-free hot loop.
//   Phase A: decode one-hot -> av[l] in {0..19, 20=masked}
//   Phase B: pack neighbor bytes per position (2 words); boundary positions
//            use the collapsed rule row = v3 * any(first/last 4 == a)
//   Phase C: warp w computes h_a on the fly for a in {4w..4w+3} and
//            accumulates 8 dot products per a into registers
//   Phase D: butterfly reduction + float4 stores
// ---------------------------------------------------------------------------
__global__ __launch_bounds__(TPB) void main_kernel(const float* __restrict__ x,
                                                   const float* __restrict__ lpm,
                                                   const float* __restrict__ pm,
                                                   const float* __restrict__ stdv,
                                                   float* __restrict__ out) {
    __shared__ float Ws[CH][L_DIM];      // 16 KB, [c][l]
    __shared__ float Vs[21 * A_DIM];     // V[i][a], row 20 = zeros
    __shared__ int   av[L_DIM];
    __shared__ uint2 nb[L_DIM];          // packed neighbor bytes

    int tid = threadIdx.x;
    int b = blockIdx.x;

    for (int i = tid; i < CH * L_DIM; i += TPB) ((float*)Ws)[i] = g_W[i];

    // V matrix (cheap; lpm/pm are L2-resident after first block)
    for (int i = tid; i < 400; i += TPB) {
        int ii = i / A_DIM, r = i % A_DIM;
        float v = 0.f;
        if (r > ii && r <= A_DIM - 2)
            v += fminf(fmaxf(lpm[ii * A_DIM + r], 0.001f), 1.0f) * pm[ii * A_DIM + r];
        if (r < ii)
            v += fminf(fmaxf(lpm[r * A_DIM + ii], 0.001f), 1.0f) * pm[r * A_DIM + ii];
        Vs[i] = v;
    }
    for (int i = tid; i < A_DIM; i += TPB) Vs[400 + i] = 0.f;

    // Phase A: decode
    const float* xb = x + (size_t)b * (L_DIM * A_DIM);
    for (int l = tid; l < L_DIM; l += TPB) {
        const float4* p = (const float4*)(xb + l * A_DIM);  // 80B rows, 16B aligned
        int aa = 20;
        #pragma unroll
        for (int j = 0; j < 5; j++) {
            float4 q = p[j];
            if (q.x != 0.f) aa = 4 * j + 0;
            if (q.y != 0.f) aa = 4 * j + 1;
            if (q.z != 0.f) aa = 4 * j + 2;
            if (q.w != 0.f) aa = 4 * j + 3;
        }
        av[l] = aa;
    }
    __syncthreads();

    // Phase B: pack. wA = self | n1m<<8 | n1p<<16 | n2m<<24
    //                wB = n2p | n3m<<8 | n3p<<16 | 31<<24   (31 = sentinel)
    // l==0:   wA = av0|av1|av2|av3 (any -> v3), wB = sentinels
    // l==511: wA = av511|av510|av509|av508,     wB = sentinels
    for (int l = tid; l < L_DIM; l += TPB) {
        unsigned wA, wB;
        if (l == 0) {
            wA = (unsigned)av[0] | ((unsigned)av[1] << 8) |
                 ((unsigned)av[2] << 16) | ((unsigned)av[3] << 24);
            wB = 0x1F1F1F1Fu;
        } else if (l == L_DIM - 1) {
            wA = (unsigned)av[511] | ((unsigned)av[510] << 8) |
                 ((unsigned)av[509] << 16) | ((unsigned)av[508] << 24);
            wB = 0x1F1F1F1Fu;
        } else {
            unsigned n1m = av[l - 1];
            unsigned n1p = av[l + 1];
            unsigned n2m = (l >= 2)   ? av[l - 2] : 31u;
            unsigned n2p = (l <= 509) ? av[l + 2] : 31u;
            unsigned n3m = (l >= 3)   ? av[l - 3] : 31u;
            unsigned n3p = (l <= 508) ? av[l + 3] : 31u;
            wA = (unsigned)av[l] | (n1m << 8) | (n1p << 16) | (n2m << 24);
            wB = n2p | (n3m << 8) | (n3p << 16) | (31u << 24);
        }
        nb[l] = make_uint2(wA, wB);
    }
    __syncthreads();

    // row kernel values (per-thread, register-only)
    float s0 = stdv[0];
    float inv = 1.0f / (2.0f * s0 * s0);
    float v1 = expf(-1.0f * inv), v2 = expf(-4.0f * inv), v3 = expf(-9.0f * inv);

    int warp = tid >> 5, lane = tid & 31;
    int abase = warp * 4;

    float acc[4][8];
    #pragma unroll
    for (int aa = 0; aa < 4; aa++)
        #pragma unroll
        for (int c = 0; c < 8; c++) acc[aa][c] = 0.f;

    unsigned aRep[4];
    #pragma unroll
    for (int aa = 0; aa < 4; aa++) aRep[aa] = (unsigned)(abase + aa) * 0x01010101u;

    // Phase C: barrier-free accumulation
    #pragma unroll 4
    for (int i = 0; i < 16; i++) {
        int l = lane + 32 * i;
        uint2 w = nb[l];
        bool spec = (l == 0) || (l == L_DIM - 1);

        float Wr[8];
        #pragma unroll
        for (int c = 0; c < 8; c++) Wr[c] = Ws[c][l];

        int s = (int)(w.x & 0xFFu);

        #pragma unroll
        for (int aa = 0; aa < 4; aa++) {
            unsigned eqA = __vcmpeq4(w.x, aRep[aa]);
            unsigned eqB = __vcmpeq4(w.y, aRep[aa]);
            bool mk3 = (eqB & 0x00FFFF00u) != 0u;
            bool mk2 = ((eqA & 0xFF000000u) | (eqB & 0x000000FFu)) != 0u;
            bool mk1 = (eqA & 0x00FFFF00u) != 0u;
            float rowg = mk3 ? v3 : (mk2 ? v2 : (mk1 ? v1 : 0.f));
            float rows = (eqA != 0u) ? v3 : 0.f;   // boundary: any of 4 -> v3
            float row = spec ? rows : rowg;
            float h = row + (((eqA & 0xFFu) != 0u) ? 1.f : 0.f)
                          + Vs[s * A_DIM + (abase + aa)];
            #pragma unroll
            for (int c = 0; c < 8; c++) acc[aa][c] += h * Wr[c];
        }
    }

    // Phase D: warp reduction + vectorized store
    #pragma unroll
    for (int aa = 0; aa < 4; aa++)
        #pragma unroll
        for (int c = 0; c < 8; c++) {
            float v = acc[aa][c];
            #pragma unroll
            for (int off = 16; off; off >>= 1)
                v += __shfl_xor_sync(0xFFFFFFFFu, v, off);
            acc[aa][c] = v;
        }
    if (lane == 0) {
        float4* o = (float4*)(out + (size_t)b * (A_DIM * CH) + abase * CH);
        #pragma unroll
        for (int aa = 0; aa < 4; aa++) {
            o[aa * 2 + 0] = make_float4(acc[aa][0], acc[aa][1], acc[aa][2], acc[aa][3]);
            o[aa * 2 + 1] = make_float4(acc[aa][4], acc[aa][5], acc[aa][6], acc[aa][7]);
        }
    }
}

// ---------------------------------------------------------------------------
// Inputs (metadata order): x, masks(unused), lpm, pm, std, w0, ws
// Output: float32 (B, A, CH) = (1024, 20, 8)
// ---------------------------------------------------------------------------
extern "C" void kernel_launch(void* const* d_in, const int* in_sizes, int n_in,
                              void* d_out, int out_size) {
    const float* x    = (const float*)d_in[0];
    const float* lpm  = (const float*)d_in[2];
    const float* pm   = (const float*)d_in[3];
    const float* stdv = (const float*)d_in[4];
    const float* w0   = (const float*)d_in[5];
    const float* ws   = (const float*)d_in[6];
    float* out = (float*)d_out;

    build_w_kernel<<<L_DIM, 256>>>(w0, ws);
    main_kernel<<<B_DIM, TPB>>>(x, lpm, pm, stdv, out);
}

// round 3
// speedup vs baseline: 2.1967x; 1.4567x over previous
#include <cuda_runtime.h>
#include <math.h>

#define A_DIM 20
#define L_DIM 512
#define CH 8
#define B_DIM 1024
#define TPB 128   // 4 warps; warp w owns amino acids 5w..5w+4

__device__ float g_W[CH * L_DIM];   // composed linear map: out[c] = sum_l W[c,l] h[l]

// ---------------------------------------------------------------------------
// f32x2 packed helpers (Blackwell FFMA2 path)
// ---------------------------------------------------------------------------
__device__ __forceinline__ unsigned long long pack2(float lo, float hi) {
    unsigned long long r;
    asm("mov.b64 %0, {%1, %2};" : "=l"(r) : "f"(lo), "f"(hi));
    return r;
}
__device__ __forceinline__ void unpack2(unsigned long long v, float& lo, float& hi) {
    asm("mov.b64 {%0, %1}, %2;" : "=f"(lo), "=f"(hi) : "l"(v));
}
__device__ __forceinline__ void ffma2(unsigned long long& d, unsigned long long a,
                                      unsigned long long b) {
    asm("fma.rn.f32x2 %0, %1, %2, %0;" : "+l"(d) : "l"(a), "l"(b));
}

// ---------------------------------------------------------------------------
// Kernel 1: W via adjoint composition. One block per output channel oc.
// Pull delta at the (8,1) output backward through pool^T / conv^T chain.
// Forward: h0(1,512) -conv w0-> pool -> (8,256) -ws[0]-> pool ... ws[7] -> (8,1)
// ---------------------------------------------------------------------------
__global__ __launch_bounds__(256) void build_w_bwd(const float* __restrict__ w0,
                                                   const float* __restrict__ ws) {
    __shared__ float GA[CH][256];
    __shared__ float GB[CH][256];
    __shared__ float sws[8 * CH * CH * 3];
    __shared__ float sw0[CH * 3];
    int tid = threadIdx.x, oc = blockIdx.x;

    for (int i = tid; i < 8 * CH * CH * 3; i += 256) sws[i] = ws[i];
    if (tid < CH * 3) sw0[tid] = w0[tid];
    if (tid < CH) GA[tid][0] = (tid == oc) ? 1.f : 0.f;
    __syncthreads();

    float (*cur)[256] = GA, (*nxt)[256] = GB;
    // backward through conv ws[j] (+ preceding pool), j = 7..0
    for (int j = 7; j >= 0; j--) {
        int L2h = 256 >> j;  // length at conv ws[j]
        const float* w = &sws[j * CH * CH * 3];
        for (int e = tid; e < CH * L2h; e += 256) {
            int ci = e / L2h, q = e % L2h;
            float acc = 0.f;
            #pragma unroll
            for (int co = 0; co < CH; co++) {
                const float* wc = w + (co * CH + ci) * 3;
                #pragma unroll
                for (int t = 0; t < 3; t++) {
                    int p = q + 1 - t;             // z position feeding y[ci][q]
                    if (p >= 0 && p < L2h) acc += wc[t] * 0.5f * cur[co][p >> 1];
                }
            }
            nxt[ci][q] = acc;
        }
        __syncthreads();
        float (*tmp)[256] = cur; cur = nxt; nxt = tmp;
    }
    // backward through pool0 + conv0 (1 -> 8): produce W[oc][q], q in [0,512)
    for (int q = tid; q < 512; q += 256) {
        float acc = 0.f;
        #pragma unroll
        for (int co = 0; co < CH; co++) {
            #pragma unroll
            for (int t = 0; t < 3; t++) {
                int p = q + 1 - t;
                if (p >= 0 && p < 512) acc += sw0[co * 3 + t] * 0.5f * cur[co][p >> 1];
            }
        }
        g_W[oc * L_DIM + q] = acc;
    }
}

// ---------------------------------------------------------------------------
// Kernel 2: main. One block per batch element.
//   A: decode one-hot -> sav[l] in {0..19, 20=masked}
//   B: per-l exclusive class masks c1/c2/c3 (bit a set => row value v1/v2/v3)
//   C: warp w, a in {5w..5w+4}: h = classSel + Vp[a][sav]; packed FFMA2 dots
//   D: butterfly reduce, float4 stores
// ---------------------------------------------------------------------------
__global__ __launch_bounds__(TPB) void main_kernel(const float* __restrict__ x,
                                                   const float* __restrict__ lpm,
                                                   const float* __restrict__ pm,
                                                   const float* __restrict__ stdv,
                                                   float* __restrict__ out) {
    __shared__ unsigned long long Wp[4 * L_DIM];  // pair j: channels (2j,2j+1), [j*512+l]
    __shared__ float Vt[A_DIM * 21];              // Vt[a*21+s] = V[s][a] + (s==a)
    __shared__ unsigned sc1[L_DIM], sc2[L_DIM], sc3[L_DIM];
    __shared__ int sav[L_DIM];

    int tid = threadIdx.x, b = blockIdx.x;

    // W channel pairs (g_W is L2-resident, 16KB)
    for (int t = tid; t < 4 * L_DIM; t += TPB) {
        int j = t >> 9, l = t & 511;
        Wp[t] = pack2(g_W[(2 * j) * L_DIM + l], g_W[(2 * j + 1) * L_DIM + l]);
    }
    // Vt with one-hot folded in
    for (int i = tid; i < A_DIM * 21; i += TPB) {
        int a = i / 21, s = i % 21;
        float v = (s == a) ? 1.f : 0.f;
        if (s < A_DIM) {
            if (a > s && a <= A_DIM - 2)
                v += fminf(fmaxf(lpm[s * A_DIM + a], 0.001f), 1.f) * pm[s * A_DIM + a];
            if (a < s)
                v += fminf(fmaxf(lpm[a * A_DIM + s], 0.001f), 1.f) * pm[a * A_DIM + s];
        }
        Vt[i] = v;
    }

    // Phase A: decode one-hot rows (80B each)
    const float* xb = x + (size_t)b * (L_DIM * A_DIM);
    #pragma unroll
    for (int r = 0; r < 4; r++) {
        int l = tid + r * TPB;
        const float4* p = (const float4*)(xb + l * A_DIM);
        int aa = 20;
        #pragma unroll
        for (int jj = 0; jj < 5; jj++) {
            float4 q = p[jj];
            if (q.x != 0.f) aa = 4 * jj + 0;
            if (q.y != 0.f) aa = 4 * jj + 1;
            if (q.z != 0.f) aa = 4 * jj + 2;
            if (q.w != 0.f) aa = 4 * jj + 3;
        }
        sav[l] = aa;
    }
    __syncthreads();

    // Phase B: exclusive class masks over a (bit 20 = masked, never tested)
    #pragma unroll
    for (int r = 0; r < 4; r++) {
        int l = tid + r * TPB;
        unsigned c1, c2, c3;
        if (l == 0) {
            c3 = (1u << sav[0]) | (1u << sav[1]) | (1u << sav[2]) | (1u << sav[3]);
            c2 = 0u; c1 = 0u;
        } else if (l == L_DIM - 1) {
            c3 = (1u << sav[511]) | (1u << sav[510]) | (1u << sav[509]) | (1u << sav[508]);
            c2 = 0u; c1 = 0u;
        } else {
            unsigned m1 = (1u << sav[l - 1]) | (1u << sav[l + 1]);
            unsigned m2 = ((l >= 2) ? (1u << sav[l - 2]) : 0u) |
                          ((l <= 509) ? (1u << sav[l + 2]) : 0u);
            unsigned m3 = ((l >= 3) ? (1u << sav[l - 3]) : 0u) |
                          ((l <= 508) ? (1u << sav[l + 3]) : 0u);
            c3 = m3;
            c2 = m2 & ~m3;
            c1 = m1 & ~(m2 | m3);
        }
        sc1[l] = c1; sc2[l] = c2; sc3[l] = c3;
    }
    __syncthreads();

    float s0 = stdv[0];
    float inv = 1.f / (2.f * s0 * s0);
    float v1 = expf(-1.f * inv), v2 = expf(-4.f * inv), v3 = expf(-9.f * inv);

    int warp = tid >> 5, lane = tid & 31;
    int abase = warp * 5;

    unsigned long long acc[5][4];
    #pragma unroll
    for (int aa = 0; aa < 5; aa++)
        #pragma unroll
        for (int j = 0; j < 4; j++) acc[aa][j] = 0ull;

    unsigned abit[5]; int vb[5];
    #pragma unroll
    for (int aa = 0; aa < 5; aa++) {
        abit[aa] = 1u << (abase + aa);
        vb[aa] = (abase + aa) * 21;
    }

    // Phase C: barrier-free packed accumulation
    #pragma unroll 2
    for (int i = 0; i < 16; i++) {
        int l = lane + 32 * i;
        unsigned c1 = sc1[l], c2 = sc2[l], c3 = sc3[l];
        int s = sav[l];
        unsigned long long w0p = Wp[l];
        unsigned long long w1p = Wp[512 + l];
        unsigned long long w2p = Wp[1024 + l];
        unsigned long long w3p = Wp[1536 + l];
        #pragma unroll
        for (int aa = 0; aa < 5; aa++) {
            float rv = (c3 & abit[aa]) ? v3
                     : (c2 & abit[aa]) ? v2
                     : (c1 & abit[aa]) ? v1 : 0.f;
            float h = rv + Vt[vb[aa] + s];
            unsigned long long hh = pack2(h, h);
            ffma2(acc[aa][0], w0p, hh);
            ffma2(acc[aa][1], w1p, hh);
            ffma2(acc[aa][2], w2p, hh);
            ffma2(acc[aa][3], w3p, hh);
        }
    }

    // Phase D: reduce + store
    #pragma unroll
    for (int aa = 0; aa < 5; aa++) {
        float v[8];
        #pragma unroll
        for (int j = 0; j < 4; j++) unpack2(acc[aa][j], v[2 * j], v[2 * j + 1]);
        #pragma unroll
        for (int c = 0; c < 8; c++) {
            #pragma unroll
            for (int off = 16; off; off >>= 1)
                v[c] += __shfl_xor_sync(0xFFFFFFFFu, v[c], off);
        }
        if (lane == 0) {
            float4* o = (float4*)(out + (size_t)b * (A_DIM * CH) + (abase + aa) * CH);
            o[0] = make_float4(v[0], v[1], v[2], v[3]);
            o[1] = make_float4(v[4], v[5], v[6], v[7]);
        }
    }
}

// ---------------------------------------------------------------------------
// Inputs (metadata order): x, masks(unused), lpm, pm, std, w0, ws
// Output: float32 (B, A, CH) = (1024, 20, 8)
// ---------------------------------------------------------------------------
extern "C" void kernel_launch(void* const* d_in, const int* in_sizes, int n_in,
                              void* d_out, int out_size) {
    const float* x    = (const float*)d_in[0];
    const float* lpm  = (const float*)d_in[2];
    const float* pm   = (const float*)d_in[3];
    const float* stdv = (const float*)d_in[4];
    const float* w0   = (const float*)d_in[5];
    const float* ws   = (const float*)d_in[6];
    float* out = (float*)d_out;

    build_w_bwd<<<CH, 256>>>(w0, ws);
    main_kernel<<<B_DIM, TPB>>>(x, lpm, pm, stdv, out);
}